// round 6
// baseline (speedup 1.0000x reference)
#include <cuda_runtime.h>
#include <cstdint>

#define N_MACRO       50000
#define D_FEAT        128
#define SEGS_PER_WARP 4
#define UNROLL        8

// lower_bound table: g_bounds[s] = first index i with seg_ids[i] >= s.
// Segment s spans [g_bounds[s], g_bounds[s+1]).
__device__ int g_bounds[N_MACRO + 1];

// ---------------------------------------------------------------------------
// Kernel 1: O(n) boundary detection on the sorted segment ids.
// Thread i writes g_bounds[s] = i for all s in (seg[i-1], seg[i]].
// Thread n-1 additionally closes the table with n.
// ---------------------------------------------------------------------------
__global__ void __launch_bounds__(256)
sp_bounds_kernel(const int* __restrict__ seg_ids, int n)
{
    int i = blockIdx.x * blockDim.x + threadIdx.x;
    if (i >= n) return;
    int cur  = __ldg(&seg_ids[i]);
    int prev = (i == 0) ? -1 : __ldg(&seg_ids[i - 1]);
    for (int s = prev + 1; s <= cur; ++s)
        g_bounds[s] = i;
    if (i == n - 1) {
        for (int s = cur + 1; s <= N_MACRO; ++s)
            g_bounds[s] = n;
    }
}

// ---------------------------------------------------------------------------
// Kernel 2: gather + segment-mean. Warp owns 4 segments; lane owns 4 dims
// (float4). 8-deep batched LDG.128 => 8 independent L2 loads in flight.
// __launch_bounds__(256, 2) gives ptxas a ~128-reg budget so the batch
// actually stays live (previous build collapsed it at 32 regs).
// ---------------------------------------------------------------------------
__global__ void __launch_bounds__(256, 2)
sp_pool_kernel(const float* __restrict__ feat,
               const int*   __restrict__ node_ids,
               float*       __restrict__ out)
{
    const int warp = (blockIdx.x * blockDim.x + threadIdx.x) >> 5;
    const int lane = threadIdx.x & 31;
    const int seg_base = warp * SEGS_PER_WARP;
    if (seg_base >= N_MACRO) return;

    // lanes 0..4 fetch the 5 bounds for this warp's 4 segments
    int b = __ldg(&g_bounds[seg_base + min(lane, SEGS_PER_WARP)]);

    #pragma unroll
    for (int g = 0; g < SEGS_PER_WARP; ++g) {
        const int s0 = __shfl_sync(0xffffffffu, b, g);
        const int s1 = __shfl_sync(0xffffffffu, b, g + 1);

        float4 acc = make_float4(0.f, 0.f, 0.f, 0.f);

        int j = s0;
        for (; j + UNROLL <= s1; j += UNROLL) {
            int nid[UNROLL];
            #pragma unroll
            for (int k = 0; k < UNROLL; ++k)
                nid[k] = __ldg(&node_ids[j + k]);
            float4 v[UNROLL];
            #pragma unroll
            for (int k = 0; k < UNROLL; ++k)
                v[k] = *reinterpret_cast<const float4*>(
                    feat + (size_t)nid[k] * D_FEAT + lane * 4);
            #pragma unroll
            for (int k = 0; k < UNROLL; ++k) {
                acc.x += v[k].x; acc.y += v[k].y;
                acc.z += v[k].z; acc.w += v[k].w;
            }
        }
        for (; j < s1; ++j) {
            int nid = __ldg(&node_ids[j]);
            float4 v = *reinterpret_cast<const float4*>(
                feat + (size_t)nid * D_FEAT + lane * 4);
            acc.x += v.x; acc.y += v.y; acc.z += v.z; acc.w += v.w;
        }

        const int cnt = s1 - s0;
        const float inv = (cnt > 0) ? (1.0f / (float)cnt) : 0.0f;
        float4 r = make_float4(acc.x * inv, acc.y * inv,
                               acc.z * inv, acc.w * inv);
        *reinterpret_cast<float4*>(
            out + (size_t)(seg_base + g) * D_FEAT + lane * 4) = r;
    }
}

// ---------------------------------------------------------------------------
// Launch
// inputs: node_feature f32 [100000*128], batch_node_ids i32 [n],
//         batch_macro_node_ids i32 [n] (sorted), num_macro_nodes (scalar)
// ---------------------------------------------------------------------------
extern "C" void kernel_launch(void* const* d_in, const int* in_sizes, int n_in,
                              void* d_out, int out_size) {
    const float* feat     = (const float*)d_in[0];
    const int*   node_ids = (const int*)d_in[1];
    const int*   seg_ids  = (const int*)d_in[2];
    float*       out      = (float*)d_out;
    const int n = in_sizes[1];

    if (n > 0) {
        sp_bounds_kernel<<<(n + 255) / 256, 256>>>(seg_ids, n);
    }

    const int n_warps  = (N_MACRO + SEGS_PER_WARP - 1) / SEGS_PER_WARP; // 12500
    const int n_blocks = (n_warps * 32 + 255) / 256;                    // 1563
    sp_pool_kernel<<<n_blocks, 256>>>(feat, node_ids, out);
}